// round 8
// baseline (speedup 1.0000x reference)
#include <cuda_runtime.h>
#include <cstdint>

// Problem constants (fixed by reference setup_inputs).
constexpr int B      = 8;
constexpr int C      = 128;
constexpr int N      = 65536;
constexpr int S      = 100;      // NUM_SEGMENTS_PER_PC
constexpr int TILE   = 64;       // points per staged tile
constexpr int PS     = 68;       // padded stage stride (floats) -> conflict-free LDS.128/STS.128
constexpr int CPB    = 37;       // chunks per batch -> grid 8*37 = 296 CTAs = 148 SMs * 2
constexpr int TPB    = N / TILE; // 1024 tiles per batch

// smem layout (floats): [slbl: 64 ints][table: 101*128][stage: 128*68]
constexpr int SM_LBL_F   = 64;                 // 64 ints = 64 float slots
constexpr int SM_TABLE_F = (S + 1) * C;        // 12928 (row 100 = junk bucket for invalid labels)
constexpr int SM_STAGE_F = C * PS;             // 8704
constexpr size_t SMEM_BYTES = (size_t)(SM_LBL_F + SM_TABLE_F + SM_STAGE_F) * 4; // 86784

// Per-CTA partial tables: 296 * 100 * 128 floats = 15.2 MB (lives in L2 between kernels).
__device__ float g_part[B * CPB * S * C];

__global__ void __launch_bounds__(128) seg_partial_kernel(
    const float* __restrict__ pf,   // (B, C, N) f32
    const int* __restrict__ ids)    // (B, N) i32  (JAX x64 disabled -> int32, NOT int64)
{
    extern __shared__ float sm[];
    int*   slbl  = (int*)sm;
    float* table = sm + SM_LBL_F;
    float* stage = sm + SM_LBL_F + SM_TABLE_F;

    const int tid   = threadIdx.x;     // 0..127 : channel id in compute phase
    const int chunk = blockIdx.x;      // 0..CPB-1
    const int b     = blockIdx.y;      // 0..B-1

    const float* pfb = pf  + (size_t)b * C * N;
    const int*   idb = ids + (size_t)b * N;

    // init private table to -inf (segment_max identity)
    #pragma unroll 4
    for (int i = tid; i < SM_TABLE_F; i += 128) table[i] = -INFINITY;
    __syncthreads();

    // tile range for this chunk (balanced integer split of 1024 tiles over 37 chunks)
    const int tBeg = (chunk       * TPB) / CPB;
    const int tEnd = ((chunk + 1) * TPB) / CPB;

    for (int t = tBeg; t < tEnd; ++t) {
        const int n0 = t * TILE;

        // ---- load phase: labels + coalesced feature tile -> padded smem stage ----
        if (tid < TILE) {
            int l = idb[n0 + tid];
            slbl[tid] = ((unsigned)l < (unsigned)S) ? l : S;   // out-of-range -> junk row
        }
        // 128 channels x 16 float4-quads; lanes cover consecutive point-quads => coalesced LDG.128
        #pragma unroll
        for (int k = 0; k < 16; ++k) {
            int q  = tid + 128 * k;          // 0..2047
            int c  = q >> 4;                 // channel
            int p4 = q & 15;                 // point-quad within tile
            float4 v = *(const float4*)(pfb + (size_t)c * N + n0 + p4 * 4);
            *(float4*)(stage + c * PS + p4 * 4) = v;
        }
        __syncthreads();

        // ---- compute phase: thread = channel tid, race-free table column ----
        #pragma unroll
        for (int p = 0; p < TILE; p += 4) {
            int4   L = *(const int4*)(slbl + p);                 // broadcast (conflict-free)
            float4 V = *(const float4*)(stage + tid * PS + p);   // conflict-free LDS.128

            int i0 = L.x * C + tid, i1 = L.y * C + tid;
            int i2 = L.z * C + tid, i3 = L.w * C + tid;
            float t0 = table[i0], t1 = table[i1], t2 = table[i2], t3 = table[i3];
            float v0 = fmaxf(V.x, t0), v1 = fmaxf(V.y, t1);
            float v2 = fmaxf(V.z, t2), v3 = fmaxf(V.w, t3);
            // forward-merge duplicate labels so the LAST store of a duplicate set
            // carries the full max (same-address stores resolve in program order)
            if (L.y == L.x) v1 = fmaxf(v1, v0);
            if (L.z == L.x) v2 = fmaxf(v2, v0);
            if (L.z == L.y) v2 = fmaxf(v2, v1);
            if (L.w == L.x) v3 = fmaxf(v3, v0);
            if (L.w == L.y) v3 = fmaxf(v3, v1);
            if (L.w == L.z) v3 = fmaxf(v3, v2);
            // predicated stores: only write when this point's raw value beats the
            // pre-read table value (expected ~ln(n) winners -> far fewer STS bytes)
            if (V.x > t0) table[i0] = v0;
            if (V.y > t1) table[i1] = v1;
            if (V.z > t2) table[i2] = v2;
            if (V.w > t3) table[i3] = v3;
        }
        __syncthreads();   // protect stage/slbl before next tile's load phase
    }

    // ---- dump private table (rows 0..S-1 only) to global scratch ----
    float* po = g_part + (size_t)(b * CPB + chunk) * (S * C);
    #pragma unroll 4
    for (int i4 = tid; i4 < (S * C) / 4; i4 += 128) {
        *(float4*)(po + i4 * 4) = *(const float4*)(table + i4 * 4);
    }
}

__global__ void __launch_bounds__(256) seg_merge_kernel(float* __restrict__ out)
{
    int idx = blockIdx.x * 256 + threadIdx.x;       // 0..102399 = (B*S, C) flattened
    int b = idx / (S * C);
    int e = idx - b * (S * C);
    const float* pb = g_part + (size_t)b * CPB * (S * C) + e;
    float m = -INFINITY;
    #pragma unroll
    for (int k = 0; k < CPB; ++k)
        m = fmaxf(m, pb[(size_t)k * (S * C)]);      // coalesced across threads
    out[idx] = m;
}

extern "C" void kernel_launch(void* const* d_in, const int* in_sizes, int n_in,
                              void* d_out, int out_size)
{
    const float* pf  = (const float*)d_in[0];   // point_features (B,C,N) f32
    const int*   ids = (const int*)d_in[2];     // box_ids_of_pts (B,N) i32
    float*       out = (float*)d_out;           // (B*S, C) f32

    cudaFuncSetAttribute(seg_partial_kernel,
                         cudaFuncAttributeMaxDynamicSharedMemorySize,
                         (int)SMEM_BYTES);

    seg_partial_kernel<<<dim3(CPB, B), 128, SMEM_BYTES>>>(pf, ids);
    seg_merge_kernel<<<(B * S * C) / 256, 256>>>(out);
}

// round 9
// speedup vs baseline: 2.2047x; 2.2047x over previous
#include <cuda_runtime.h>
#include <cstdint>

// Problem constants (fixed by reference setup_inputs).
constexpr int B    = 8;
constexpr int C    = 128;
constexpr int N    = 65536;
constexpr int S    = 100;        // NUM_SEGMENTS_PER_PC
constexpr int TILE = 32;         // points per staged tile
constexpr int PS   = 36;         // padded stage stride (floats): 144B = 9*16 (cp.async-aligned),
                                 // bank stride 4 -> conflict-free LDS.128 phases
constexpr int CPB  = 37;         // chunks per batch -> grid 8*37 = 296 CTAs = 148 SMs * 2
constexpr int TPB  = N / TILE;   // 2048 tiles per batch

// smem (floats): [slbl: 2x32 ints][table: 101*128][stage0: 128*36][stage1: 128*36]
constexpr int SM_LBL_I   = 64;               // two 32-int label buffers
constexpr int SM_TABLE_F = (S + 1) * C;      // 12928 (row 100 = junk bucket)
constexpr int SM_STAGE_F = C * PS;           // 4608 per buffer
constexpr size_t SMEM_BYTES = (size_t)(SM_LBL_I + SM_TABLE_F + 2 * SM_STAGE_F) * 4; // 88832

// Per-CTA partial tables: 296 * 100 * 128 floats = 15.2 MB (L2-resident between kernels).
__device__ float g_part[B * CPB * S * C];

#define CP_ASYNC16(dst_sa, src)                                            \
    asm volatile("cp.async.cg.shared.global [%0], [%1], 16;" ::            \
                 "r"(dst_sa), "l"(src))
#define CP_COMMIT()  asm volatile("cp.async.commit_group;")
#define CP_WAIT(n)   asm volatile("cp.async.wait_group %0;" :: "n"(n))

__global__ void __launch_bounds__(128) seg_partial_kernel(
    const float* __restrict__ pf,   // (B, C, N) f32
    const int* __restrict__ ids)    // (B, N) i32 (JAX x64 disabled)
{
    extern __shared__ float sm[];
    int*   slbl  = (int*)sm;                       // [2][32]
    float* table = sm + SM_LBL_I;                  // [101][128]
    float* stage = sm + SM_LBL_I + SM_TABLE_F;     // [2][128][36]

    const int tid   = threadIdx.x;   // channel id in compute phase
    const int chunk = blockIdx.x;
    const int b     = blockIdx.y;

    const float* pfb = pf  + (size_t)b * C * N;
    const int*   idb = ids + (size_t)b * N;

    const uint32_t slbl_sa  = (uint32_t)__cvta_generic_to_shared(slbl);
    const uint32_t stage_sa = (uint32_t)__cvta_generic_to_shared(stage);

    // init private table to -inf
    #pragma unroll 4
    for (int i = tid; i < SM_TABLE_F; i += 128) table[i] = -INFINITY;

    const int tBeg = (chunk       * TPB) / CPB;
    const int tEnd = ((chunk + 1) * TPB) / CPB;

    // async prefetch of one tile into buffer `buf` (no data registers, MLP=8/thread)
    auto prefetch = [&](int t, int buf) {
        const int n0 = t * TILE;
        const uint32_t sbase = stage_sa + (uint32_t)buf * SM_STAGE_F * 4;
        #pragma unroll
        for (int k = 0; k < 8; ++k) {
            int q  = tid + 128 * k;        // 0..1023
            int c  = q >> 3;               // channel
            int p4 = q & 7;                // float4-quad within tile (32 floats/row)
            CP_ASYNC16(sbase + (uint32_t)(c * PS + p4 * 4) * 4,
                       pfb + (size_t)c * N + n0 + p4 * 4);
        }
        if (tid < 8)   // 32 labels = 128B
            CP_ASYNC16(slbl_sa + (uint32_t)buf * 128 + tid * 16,
                       idb + n0 + tid * 4);
    };

    prefetch(tBeg, tBeg & 1);
    CP_COMMIT();

    for (int t = tBeg; t < tEnd; ++t) {
        const int cur = t & 1;
        if (t + 1 < tEnd) {
            prefetch(t + 1, cur ^ 1);
            CP_COMMIT();
            CP_WAIT(1);              // tile t landed
        } else {
            CP_WAIT(0);
        }
        __syncthreads();             // stage[cur]/slbl[cur] visible to all

        const float* st = stage + cur * SM_STAGE_F + tid * PS;
        const int*   lb = slbl  + cur * 32;

        #pragma unroll
        for (int p = 0; p < TILE; p += 4) {
            int4   L = *(const int4*)(lb + p);          // broadcast
            float4 V = *(const float4*)(st + p);        // conflict-free LDS.128

            // clamp stray labels (e.g. -1) into junk row S
            if ((unsigned)L.x >= (unsigned)S) L.x = S;
            if ((unsigned)L.y >= (unsigned)S) L.y = S;
            if ((unsigned)L.z >= (unsigned)S) L.z = S;
            if ((unsigned)L.w >= (unsigned)S) L.w = S;

            int i0 = L.x * C + tid, i1 = L.y * C + tid;
            int i2 = L.z * C + tid, i3 = L.w * C + tid;
            float t0 = table[i0], t1 = table[i1], t2 = table[i2], t3 = table[i3];
            float v0 = fmaxf(V.x, t0), v1 = fmaxf(V.y, t1);
            float v2 = fmaxf(V.z, t2), v3 = fmaxf(V.w, t3);
            // forward-merge duplicate labels; last store of a duplicate set wins
            if (L.y == L.x) v1 = fmaxf(v1, v0);
            if (L.z == L.x) v2 = fmaxf(v2, v0);
            if (L.z == L.y) v2 = fmaxf(v2, v1);
            if (L.w == L.x) v3 = fmaxf(v3, v0);
            if (L.w == L.y) v3 = fmaxf(v3, v1);
            if (L.w == L.z) v3 = fmaxf(v3, v2);
            // predicated winner-only stores
            if (V.x > t0) table[i0] = v0;
            if (V.y > t1) table[i1] = v1;
            if (V.z > t2) table[i2] = v2;
            if (V.w > t3) table[i3] = v3;
        }
        __syncthreads();   // compute done before next prefetch overwrites this buffer
    }

    // dump private table (rows 0..S-1) to global scratch
    float* po = g_part + (size_t)(b * CPB + chunk) * (S * C);
    #pragma unroll 4
    for (int i4 = tid; i4 < (S * C) / 4; i4 += 128)
        *(float4*)(po + i4 * 4) = *(const float4*)(table + i4 * 4);
}

__global__ void __launch_bounds__(256) seg_merge_kernel(float* __restrict__ out)
{
    int idx = blockIdx.x * 256 + threadIdx.x;   // 0..B*S*C-1
    int b = idx / (S * C);
    int e = idx - b * (S * C);
    const float* pb = g_part + (size_t)b * CPB * (S * C) + e;

    // front-batch all 37 loads (MLP=37) before reducing
    float v[CPB];
    #pragma unroll
    for (int k = 0; k < CPB; ++k) v[k] = pb[(size_t)k * (S * C)];
    float m = -INFINITY;
    #pragma unroll
    for (int k = 0; k < CPB; ++k) m = fmaxf(m, v[k]);
    out[idx] = m;
}

extern "C" void kernel_launch(void* const* d_in, const int* in_sizes, int n_in,
                              void* d_out, int out_size)
{
    const float* pf  = (const float*)d_in[0];   // point_features (B,C,N) f32
    const int*   ids = (const int*)d_in[2];     // box_ids_of_pts (B,N) i32
    float*       out = (float*)d_out;           // (B*S, C) f32

    cudaFuncSetAttribute(seg_partial_kernel,
                         cudaFuncAttributeMaxDynamicSharedMemorySize,
                         (int)SMEM_BYTES);

    seg_partial_kernel<<<dim3(CPB, B), 128, SMEM_BYTES>>>(pf, ids);
    seg_merge_kernel<<<(B * S * C) / 256, 256>>>(out);
}

// round 10
// speedup vs baseline: 2.3597x; 1.0703x over previous
#include <cuda_runtime.h>
#include <cstdint>

// Problem constants (fixed by reference setup_inputs).
constexpr int B      = 8;
constexpr int C      = 128;
constexpr int N      = 65536;
constexpr int S      = 100;       // NUM_SEGMENTS_PER_PC
constexpr int TILE   = 32;        // points per staged tile
constexpr int PS     = 36;        // padded stage stride (floats): 144B, 16B-aligned, conflict-free
constexpr int STAGES = 3;         // cp.async ring depth -> prefetch distance 2 tiles
constexpr int CPB    = 37;        // chunks per batch -> grid 8*37 = 296 CTAs = 148 SMs * 2
constexpr int TPB    = N / TILE;  // 2048 tiles per batch

// smem (floats): [slbl: 3x32 ints][table: 101*128][stage: 3x128x36]
constexpr int SM_LBL_I   = STAGES * TILE;     // 96 ints
constexpr int SM_TABLE_F = (S + 1) * C;       // 12928 (row 100 = junk bucket)
constexpr int SM_STAGE_F = C * PS;            // 4608 per buffer
constexpr size_t SMEM_BYTES =
    (size_t)(SM_LBL_I + SM_TABLE_F + STAGES * SM_STAGE_F) * 4;   // 107392 B (~105 KB)

// Per-CTA partial tables: 296 * 100 * 128 floats = 15.2 MB.
__device__ float g_part[B * CPB * S * C];

#define CP_ASYNC16(dst_sa, src)                                            \
    asm volatile("cp.async.cg.shared.global [%0], [%1], 16;" ::            \
                 "r"(dst_sa), "l"(src))
#define CP_COMMIT()  asm volatile("cp.async.commit_group;")
#define CP_WAIT(n)   asm volatile("cp.async.wait_group %0;" :: "n"(n))

__global__ void __launch_bounds__(128) seg_partial_kernel(
    const float* __restrict__ pf,   // (B, C, N) f32
    const int* __restrict__ ids)    // (B, N) i32 (JAX x64 disabled)
{
    extern __shared__ float sm[];
    int*   slbl  = (int*)sm;                       // [STAGES][32]
    float* table = sm + SM_LBL_I;                  // [101][128] -- column tid is THREAD-PRIVATE
    float* stage = sm + SM_LBL_I + SM_TABLE_F;     // [STAGES][128][36]

    const int tid   = threadIdx.x;   // channel id in compute phase
    const int chunk = blockIdx.x;
    const int b     = blockIdx.y;

    const float* pfb = pf  + (size_t)b * C * N;
    const int*   idb = ids + (size_t)b * N;

    const uint32_t slbl_sa  = (uint32_t)__cvta_generic_to_shared(slbl);
    const uint32_t stage_sa = (uint32_t)__cvta_generic_to_shared(stage);

    // init private table column to -inf (column tid touched only by thread tid:
    // no barrier ever needed for the table)
    #pragma unroll 4
    for (int i = tid; i < SM_TABLE_F; i += 128) table[i] = -INFINITY;

    const int tBeg = (chunk       * TPB) / CPB;
    const int tEnd = ((chunk + 1) * TPB) / CPB;

    // async prefetch of one tile into ring buffer `buf` (MLP=8/thread, no data regs)
    auto prefetch = [&](int t, int buf) {
        const int n0 = t * TILE;
        const uint32_t sbase = stage_sa + (uint32_t)buf * SM_STAGE_F * 4;
        #pragma unroll
        for (int k = 0; k < 8; ++k) {
            int q  = tid + 128 * k;        // 0..1023
            int c  = q >> 3;               // channel
            int p4 = q & 7;                // float4-quad (32 floats per channel-row)
            CP_ASYNC16(sbase + (uint32_t)(c * PS + p4 * 4) * 4,
                       pfb + (size_t)c * N + n0 + p4 * 4);
        }
        if (tid < 8)   // 32 labels = 128B
            CP_ASYNC16(slbl_sa + (uint32_t)buf * 128 + tid * 16,
                       idb + n0 + tid * 4);
    };

    // prologue: two groups in flight (one commit per tile, always)
    prefetch(tBeg, 0);
    CP_COMMIT();
    if (tBeg + 1 < tEnd) prefetch(tBeg + 1, 1 % STAGES);
    CP_COMMIT();

    for (int t = tBeg; t < tEnd; ++t) {
        const int cur = (t - tBeg) % STAGES;

        CP_WAIT(1);        // group for tile t has landed (exactly 2 groups in flight)
        __syncthreads();   // publish buf[cur]; also licenses reuse of buf[(cur+2)%STAGES]
                           // (its compute finished before the PREVIOUS barrier)

        if (t + 2 < tEnd) prefetch(t + 2, (cur + 2) % STAGES);
        CP_COMMIT();       // empty group near the tail keeps wait_group accounting aligned

        const float* st = stage + cur * SM_STAGE_F + tid * PS;
        const int*   lb = slbl  + cur * TILE;

        #pragma unroll
        for (int p = 0; p < TILE; p += 4) {
            int4   L = *(const int4*)(lb + p);          // broadcast
            float4 V = *(const float4*)(st + p);        // conflict-free LDS.128

            if ((unsigned)L.x >= (unsigned)S) L.x = S;  // stray labels -> junk row
            if ((unsigned)L.y >= (unsigned)S) L.y = S;
            if ((unsigned)L.z >= (unsigned)S) L.z = S;
            if ((unsigned)L.w >= (unsigned)S) L.w = S;

            int i0 = L.x * C + tid, i1 = L.y * C + tid;
            int i2 = L.z * C + tid, i3 = L.w * C + tid;
            float t0 = table[i0], t1 = table[i1], t2 = table[i2], t3 = table[i3];
            float v0 = fmaxf(V.x, t0), v1 = fmaxf(V.y, t1);
            float v2 = fmaxf(V.z, t2), v3 = fmaxf(V.w, t3);
            // forward-merge duplicate labels; last store of a duplicate set wins
            if (L.y == L.x) v1 = fmaxf(v1, v0);
            if (L.z == L.x) v2 = fmaxf(v2, v0);
            if (L.z == L.y) v2 = fmaxf(v2, v1);
            if (L.w == L.x) v3 = fmaxf(v3, v0);
            if (L.w == L.y) v3 = fmaxf(v3, v1);
            if (L.w == L.z) v3 = fmaxf(v3, v2);
            // predicated winner-only stores
            if (V.x > t0) table[i0] = v0;
            if (V.y > t1) table[i1] = v1;
            if (V.z > t2) table[i2] = v2;
            if (V.w > t3) table[i3] = v3;
        }
        // no trailing barrier: the next iteration's single barrier covers buffer reuse
    }

    // dump private table (rows 0..S-1) to global scratch
    float* po = g_part + (size_t)(b * CPB + chunk) * (S * C);
    #pragma unroll 4
    for (int i4 = tid; i4 < (S * C) / 4; i4 += 128)
        *(float4*)(po + i4 * 4) = *(const float4*)(table + i4 * 4);
}

__global__ void __launch_bounds__(256) seg_merge_kernel(float* __restrict__ out)
{
    int idx = blockIdx.x * 256 + threadIdx.x;   // 0..B*S*C-1
    int b = idx / (S * C);
    int e = idx - b * (S * C);
    const float* pb = g_part + (size_t)b * CPB * (S * C) + e;

    // 4 independent accumulator chains -> MLP ~4x a rolling max
    float m0 = -INFINITY, m1 = -INFINITY, m2 = -INFINITY, m3 = -INFINITY;
    int k = 0;
    #pragma unroll
    for (; k + 4 <= CPB; k += 4) {
        m0 = fmaxf(m0, pb[(size_t)(k + 0) * (S * C)]);
        m1 = fmaxf(m1, pb[(size_t)(k + 1) * (S * C)]);
        m2 = fmaxf(m2, pb[(size_t)(k + 2) * (S * C)]);
        m3 = fmaxf(m3, pb[(size_t)(k + 3) * (S * C)]);
    }
    #pragma unroll
    for (; k < CPB; ++k) m0 = fmaxf(m0, pb[(size_t)k * (S * C)]);
    out[idx] = fmaxf(fmaxf(m0, m1), fmaxf(m2, m3));
}

extern "C" void kernel_launch(void* const* d_in, const int* in_sizes, int n_in,
                              void* d_out, int out_size)
{
    const float* pf  = (const float*)d_in[0];   // point_features (B,C,N) f32
    const int*   ids = (const int*)d_in[2];     // box_ids_of_pts (B,N) i32
    float*       out = (float*)d_out;           // (B*S, C) f32

    cudaFuncSetAttribute(seg_partial_kernel,
                         cudaFuncAttributeMaxDynamicSharedMemorySize,
                         (int)SMEM_BYTES);

    seg_partial_kernel<<<dim3(CPB, B), 128, SMEM_BYTES>>>(pf, ids);
    seg_merge_kernel<<<(B * S * C) / 256, 256>>>(out);
}